// round 6
// baseline (speedup 1.0000x reference)
#include <cuda_runtime.h>
#include <cuda_fp16.h>

#define BB   256
#define TT   512
#define HH   128
#define G4   512
#define IND  10
#define TRG  32

typedef unsigned long long u64;

// ---------------- packed f32x2 helpers ----------------
__device__ __forceinline__ void ffma2(u64& acc, u64 a, u64 b) {
    asm("fma.rn.f32x2 %0, %1, %2, %0;" : "+l"(acc) : "l"(a), "l"(b));
}
__device__ __forceinline__ u64 pk(float lo, float hi) {
    u64 d; asm("mov.b64 %0, {%1, %2};" : "=l"(d) : "f"(lo), "f"(hi)); return d;
}
__device__ __forceinline__ float psum(u64 a) {
    float x, y; asm("mov.b64 {%0, %1}, %2;" : "=f"(x), "=f"(y) : "l"(a));
    return x + y;
}
__device__ __forceinline__ u64 h2u64(unsigned int h2bits) {
    __half2 h = *reinterpret_cast<__half2*>(&h2bits);
    float2 f = __half22float2(h);
    u64 d; asm("mov.b64 %0, {%1, %2};" : "=l"(d) : "f"(f.x), "f"(f.y)); return d;
}

// ---------------- device-global scratch ----------------
// w_hh fp32 rearranged for thread-per-gate access (g = tid):
// g_wreg_f: k in [0,64) as u64 k-pairs:   [(L*32 + (k>>1))*512 + g]
// g_wsm_f:  k in [64,128) as float4:      [(L*16 + ((k-64)>>2))*512 + g]
__device__ float  g_wreg_f[2 * 32 * 512 * 2];
__device__ float  g_wsm_f[2 * 16 * 512 * 4];
__device__ __half g_wih1h[G4 * HH];               // fp16 blocked, xgate1 only
__device__ float  g_h1[(size_t)BB * TT * HH];
__device__ float  g_xg1[(size_t)BB * TT * G4];
__device__ float  g_h2last[BB * HH];

__global__ void prep_kernel(const float* __restrict__ w_hh0,
                            const float* __restrict__ w_hh1,
                            const float* __restrict__ w_ih1)
{
    int idx = blockIdx.x * blockDim.x + threadIdx.x;   // 196608 threads
    if (idx < 131072) {
        int L = idx >> 16;
        int e = idx & 65535;
        int g = e >> 7;
        int k = e & 127;
        float v = (L ? w_hh1 : w_hh0)[e];
        if (k < 64)
            g_wreg_f[((L * 32 + (k >> 1)) * 512 + g) * 2 + (k & 1)] = v;
        else
            g_wsm_f[((L * 16 + ((k - 64) >> 2)) * 512 + g) * 4 + ((k - 64) & 3)] = v;
    } else {
        int e = idx - 131072;
        int g = e >> 7;
        int k = e & 127;
        int dst = ((k >> 3) << 12) + (g << 3) + (k & 7);
        g_wih1h[dst] = __float2half(w_ih1[e]);
    }
}

__device__ __forceinline__ float sigf(float x) {
    return 1.0f / (1.0f + __expf(-x));
}
__device__ __forceinline__ float tanhfast(float x) {
    return 2.0f / (1.0f + __expf(-2.0f * x)) - 1.0f;
}

// ---------------- LSTM recurrence ----------------
// 128 CTAs x 2 batch rows, 512 threads (16 warps = 4/SMSP). Thread = gate tid,
// both rows. k<64: fp32 weights in regs. k in [64,128): fp32 weights in smem.
// All math fp32-exact. Activations by threads 0..255 (thread = (row,unit)).
// smem (bytes):
//   [0,131072)        w_hh fp32 k-hi half, float4 ws4[c*512+g], c=0..15
//   [131072,151552)   wih0 fp32 k-major [10][512]   (layer0 only)
//   [151552,153600)   bias [512]                    (layer0 only)
//   [153600,154624)   hs [2 rows][128]
//   [154624,158720)   gs [2 rows][512]
//   [158720,158848)   xs [2 rows][16]               (layer0 only)
#define LSTM_SMEM 158848

template<int LAYER>
__global__ void __launch_bounds__(512, 1) lstm_layer_kernel(
    const float* __restrict__ x,
    const float* __restrict__ w_ih,
    const float* __restrict__ b_ih,
    const float* __restrict__ b_hh)
{
    extern __shared__ char smem[];
    float* ws     = (float*)smem;
    float* wih_s  = (float*)(smem + 131072);
    float* bias_s = (float*)(smem + 151552);
    float* hs     = (float*)(smem + 153600);
    float* gs     = (float*)(smem + 154624);
    float* xs     = (float*)(smem + 158720);

    const int tid = threadIdx.x;        // = gate index
    const int bb  = blockIdx.x;

    // k<64 fp32 weights into registers (coalesced u64 loads)
    u64 wreg[32];
    {
        const u64* wr = (const u64*)g_wreg_f;
        #pragma unroll
        for (int i = 0; i < 32; i++)
            wreg[i] = wr[(LAYER * 32 + i) * 512 + tid];
    }

    // k in [64,128) fp32 weights into smem (coalesced, thread-indexed)
    {
        float4*       ws4 = (float4*)ws;
        const float4* gw4 = (const float4*)g_wsm_f;
        #pragma unroll
        for (int c = 0; c < 16; c++)
            ws4[c * 512 + tid] = gw4[(LAYER * 16 + c) * 512 + tid];
    }

    if (LAYER == 0) {
        #pragma unroll
        for (int j = 0; j < IND; j++)
            wih_s[j * 512 + tid] = w_ih[tid * IND + j];
        bias_s[tid] = b_ih[tid] + b_hh[tid];
    }
    if (tid < 256) hs[tid] = 0.0f;

    float creg = 0.0f;                  // cell state: act thread = (row, unit)
    const int r_act = tid >> 7;
    const int j_act = tid & 127;

    // prefetch t=0 step inputs
    float xg0 = 0.0f, xg1v = 0.0f;
    int xr = 0, xj = 0;
    if (LAYER == 0) {
        if (tid < 2 * IND) {
            xr = tid / IND; xj = tid - xr * IND;
            xs[xr * 16 + xj] = x[(size_t)(2 * bb + xr) * (TT * IND) + xj];
        }
    } else {
        xg0  = g_xg1[((size_t)(2 * bb + 0) * TT + 0) * G4 + tid];
        xg1v = g_xg1[((size_t)(2 * bb + 1) * TT + 0) * G4 + tid];
    }
    __syncthreads();

    const ulonglong2* h0v = (const ulonglong2*)hs;          // row0, 4 floats each
    const ulonglong2* h1v = (const ulonglong2*)(hs + 128);  // row1
    const ulonglong2* wsu = (const ulonglong2*)ws;

    for (int t = 0; t < TT; t++) {
        // [A] prefetch next step's inputs
        float nx = 0.0f, n0 = 0.0f, n1 = 0.0f;
        if (LAYER == 0) {
            if (tid < 2 * IND && t + 1 < TT)
                nx = x[(size_t)(2 * bb + xr) * (TT * IND) + (size_t)(t + 1) * IND + xj];
        } else {
            if (t + 1 < TT) {
                n0 = g_xg1[((size_t)(2 * bb + 0) * TT + (t + 1)) * G4 + tid];
                n1 = g_xg1[((size_t)(2 * bb + 1) * TT + (t + 1)) * G4 + tid];
            }
        }

        // [B] initial scalar part (bias + x-projection for layer0)
        float i0, i1;
        if (LAYER == 0) {
            float bv = bias_s[tid];
            i0 = bv; i1 = bv;
            #pragma unroll
            for (int j = 0; j < IND; j++) {
                float wv = wih_s[j * 512 + tid];
                i0 = fmaf(xs[j],      wv, i0);
                i1 = fmaf(xs[16 + j], wv, i1);
            }
        } else {
            i0 = xg0; i1 = xg1v;
        }

        u64 a0a = pk(i0, 0.0f), a0b = pk(0.0f, 0.0f);
        u64 a1a = pk(i1, 0.0f), a1b = pk(0.0f, 0.0f);

        // k in [0,64): register weights
        #pragma unroll
        for (int i = 0; i < 16; i++) {
            ulonglong2 h0 = h0v[i];
            ulonglong2 h1 = h1v[i];
            ffma2(a0a, h0.x, wreg[2 * i]);
            ffma2(a0b, h0.y, wreg[2 * i + 1]);
            ffma2(a1a, h1.x, wreg[2 * i]);
            ffma2(a1b, h1.y, wreg[2 * i + 1]);
        }

        // k in [64,128): fp32 smem weights (conflict-free, no conversions)
        #pragma unroll
        for (int c = 0; c < 16; c++) {
            ulonglong2 w  = wsu[c * 512 + tid];   // k = 64+4c .. 64+4c+3
            ulonglong2 h0 = h0v[16 + c];
            ulonglong2 h1 = h1v[16 + c];
            ffma2(a0a, h0.x, w.x);
            ffma2(a0b, h0.y, w.y);
            ffma2(a1a, h1.x, w.x);
            ffma2(a1b, h1.y, w.y);
        }

        gs[tid]       = psum(a0a) + psum(a0b);
        gs[512 + tid] = psum(a1a) + psum(a1b);
        __syncthreads();

        // [C] activations + state update (threads 0..255)
        if (tid < 256) {
            const float* gr = gs + r_act * 512;
            float iv = sigf(gr[j_act]);
            float fv = sigf(gr[128 + j_act]);
            float gv = tanhfast(gr[256 + j_act]);
            float ov = sigf(gr[384 + j_act]);
            creg = fv * creg + iv * gv;
            float hn = ov * tanhfast(creg);
            hs[r_act * 128 + j_act] = hn;
            if (LAYER == 0) {
                g_h1[((size_t)(2 * bb + r_act) * TT + t) * HH + j_act] = hn;
            } else if (t == TT - 1) {
                g_h2last[(2 * bb + r_act) * HH + j_act] = hn;
            }
        }
        if (LAYER == 0) {
            if (tid < 2 * IND) xs[xr * 16 + xj] = nx;
        } else {
            xg0 = n0; xg1v = n1;
        }
        __syncthreads();
    }
}

// ---------------- layer-1 input projection GEMM (R4-proven version) ----------------
#define XG_SMEM (131072 + TRG * HH * 4)

__global__ void __launch_bounds__(512, 1) xgate1_kernel(
    const float* __restrict__ b_ih1, const float* __restrict__ b_hh1)
{
    extern __shared__ char smem[];
    __half* wsm = (__half*)smem;
    float*  h_s = (float*)(smem + 131072);

    const int tid = threadIdx.x;

    uint4*       wsm4 = (uint4*)wsm;
    const uint4* gw4  = (const uint4*)g_wih1h;
    #pragma unroll
    for (int i = 0; i < 16; i++)
        wsm4[i * 512 + tid] = gw4[i * 512 + tid];

    const size_t base = (size_t)blockIdx.x * TRG * HH;
    float4*       h_s4 = (float4*)h_s;
    const float4* src4 = (const float4*)(g_h1 + base);
    #pragma unroll
    for (int i = 0; i < (TRG * HH / 4) / 512; i++)
        h_s4[i * 512 + tid] = src4[i * 512 + tid];
    __syncthreads();

    float bv = b_ih1[tid] + b_hh1[tid];
    u64 acc[TRG];
    #pragma unroll
    for (int r = 0; r < TRG; r++) acc[r] = pk(bv, 0.0f);

    #pragma unroll 1
    for (int c = 0; c < 16; c++) {
        uint4 wp = wsm4[c * 512 + tid];
        u64 w0 = h2u64(wp.x);
        u64 w1 = h2u64(wp.y);
        u64 w2 = h2u64(wp.z);
        u64 w3 = h2u64(wp.w);
        #pragma unroll
        for (int r = 0; r < TRG; r++) {
            ulonglong2 ha = *(const ulonglong2*)(h_s + r * HH + c * 8);
            ulonglong2 hb = *(const ulonglong2*)(h_s + r * HH + c * 8 + 4);
            ffma2(acc[r], ha.x, w0);
            ffma2(acc[r], ha.y, w1);
            ffma2(acc[r], hb.x, w2);
            ffma2(acc[r], hb.y, w3);
        }
    }

    #pragma unroll
    for (int r = 0; r < TRG; r++)
        g_xg1[((size_t)blockIdx.x * TRG + r) * G4 + tid] = psum(acc[r]);
}

// ---------------- final FC ----------------
__global__ void fc_kernel(const float* __restrict__ fc_w,
                          const float* __restrict__ fc_b,
                          float* __restrict__ out)
{
    int b = threadIdx.x;
    const float* hrow = g_h2last + b * HH;
    #pragma unroll
    for (int c = 0; c < 10; c++) {
        float acc = fc_b[c];
        #pragma unroll
        for (int k = 0; k < HH; k++)
            acc = fmaf(hrow[k], fc_w[c * HH + k], acc);
        out[b * 10 + c] = acc;
    }
}

extern "C" void kernel_launch(void* const* d_in, const int* in_sizes, int n_in,
                              void* d_out, int out_size)
{
    const float* x     = (const float*)d_in[0];
    const float* w_ih0 = (const float*)d_in[1];
    const float* w_hh0 = (const float*)d_in[2];
    const float* b_ih0 = (const float*)d_in[3];
    const float* b_hh0 = (const float*)d_in[4];
    const float* w_ih1 = (const float*)d_in[5];
    const float* w_hh1 = (const float*)d_in[6];
    const float* b_ih1 = (const float*)d_in[7];
    const float* b_hh1 = (const float*)d_in[8];
    const float* fc_w  = (const float*)d_in[9];
    const float* fc_b  = (const float*)d_in[10];
    float* out = (float*)d_out;

    cudaFuncSetAttribute(lstm_layer_kernel<0>,
                         cudaFuncAttributeMaxDynamicSharedMemorySize, LSTM_SMEM);
    cudaFuncSetAttribute(lstm_layer_kernel<1>,
                         cudaFuncAttributeMaxDynamicSharedMemorySize, LSTM_SMEM);
    cudaFuncSetAttribute(xgate1_kernel,
                         cudaFuncAttributeMaxDynamicSharedMemorySize, XG_SMEM);

    prep_kernel<<<768, 256>>>(w_hh0, w_hh1, w_ih1);
    lstm_layer_kernel<0><<<BB / 2, 512, LSTM_SMEM>>>(x, w_ih0, b_ih0, b_hh0);
    xgate1_kernel<<<(BB * TT) / TRG, 512, XG_SMEM>>>(b_ih1, b_hh1);
    lstm_layer_kernel<1><<<BB / 2, 512, LSTM_SMEM>>>(nullptr, nullptr, nullptr, nullptr);
    fc_kernel<<<1, 256>>>(fc_w, fc_b, out);
}